// round 3
// baseline (speedup 1.0000x reference)
#include <cuda_runtime.h>
#include <cuda_bf16.h>

// CapsuleLinear k-means routing (dot sim, no squash) — GB300 sm_103a, round 3.
//
// Reformulation (priors never materialized):
//   logits[n] = (W^T out_n)·x[n],  out ∝ W t,  t = Σ_n e_n x[n]
//   v = W^T(Wt)/||Wt|| = M t / sqrt(t^T M t),  M = W^T W  (8x8, per-CTA const)
// Softmax max-free and unnormalized except at the end (scale invariance).
//
// Round-3 changes: 64 threads x 18 rows (halves chip-wide shfl/barrier fixed
// cost), rows paired into f32x2 registers and processed with fma.rn.f32x2
// (FFMA2 — half the FMA instruction count), rsqrt for the normalize.

namespace {
constexpr int BATCH   = 64;
constexpr int N_IN    = 1152;
constexpr int LI      = 8;
constexpr int LO      = 16;
constexpr int O_CAPS  = 64;
constexpr int THREADS = 64;
constexpr int NPT     = 18;           // 1152 = 64 * 18
constexpr int NPAIR   = NPT / 2;      // 9 f32x2 row-pairs
constexpr int NW      = THREADS / 32; // 2 warps
constexpr unsigned FULL = 0xffffffffu;
}

// ---- f32x2 packed helpers (FFMA2/FADD2/FMUL2 — PTX-only on sm_103a) ----
__device__ __forceinline__ unsigned long long pk2(float lo, float hi) {
    unsigned long long r;
    asm("mov.b64 %0, {%1, %2};" : "=l"(r) : "f"(lo), "f"(hi));
    return r;
}
__device__ __forceinline__ void upk2(float& lo, float& hi, unsigned long long v) {
    asm("mov.b64 {%0, %1}, %2;" : "=f"(lo), "=f"(hi) : "l"(v));
}
__device__ __forceinline__ unsigned long long ffma2(unsigned long long a,
                                                    unsigned long long b,
                                                    unsigned long long c) {
    unsigned long long d;
    asm("fma.rn.f32x2 %0, %1, %2, %3;" : "=l"(d) : "l"(a), "l"(b), "l"(c));
    return d;
}
__device__ __forceinline__ unsigned long long fadd2(unsigned long long a,
                                                    unsigned long long b) {
    unsigned long long d;
    asm("add.rn.f32x2 %0, %1, %2;" : "=l"(d) : "l"(a), "l"(b));
    return d;
}
__device__ __forceinline__ unsigned long long fmul2(unsigned long long a,
                                                    unsigned long long b) {
    unsigned long long d;
    asm("mul.rn.f32x2 %0, %1, %2;" : "=l"(d) : "l"(a), "l"(b));
    return d;
}

__global__ __launch_bounds__(THREADS)
void caps_route_kernel(const float* __restrict__ x,
                       const float* __restrict__ wgt,
                       float* __restrict__ out_c,
                       float* __restrict__ out_p)
{
    const int bo   = blockIdx.x;          // b*64 + o (o fastest -> L2 reuse of x[b])
    const int b    = bo >> 6;
    const int o    = bo & 63;
    const int tid  = threadIdx.x;
    const int lane = tid & 31;
    const int warp = tid >> 5;

    __shared__ float ws[LO * LI];          // weight[o]
    __shared__ float Msh[LI * LI];         // M = W^T W
    __shared__ float tred[2][NW][LI];      // double-buffered t partials
    __shared__ float sred[NW];             // final softmax sum partials

    if (tid < LO * LI)       ws[tid]      = wgt[o * LO * LI + tid];
    if (tid + 64 < LO * LI)  ws[tid + 64] = wgt[o * LO * LI + tid + 64];

    // ---- x rows in packed f32x2 registers: pair p holds rows (tid+2p*64, tid+(2p+1)*64) ----
    unsigned long long xp[NPAIR][LI];
    const float4* xb = reinterpret_cast<const float4*>(x + (size_t)b * N_IN * LI);
    #pragma unroll
    for (int p = 0; p < NPAIR; p++) {
        const int n0 = tid + (2 * p) * THREADS;
        const int n1 = n0 + THREADS;
        float4 a0 = xb[2 * n0], b0 = xb[2 * n0 + 1];
        float4 a1 = xb[2 * n1], b1 = xb[2 * n1 + 1];
        xp[p][0] = pk2(a0.x, a1.x); xp[p][1] = pk2(a0.y, a1.y);
        xp[p][2] = pk2(a0.z, a1.z); xp[p][3] = pk2(a0.w, a1.w);
        xp[p][4] = pk2(b0.x, b1.x); xp[p][5] = pk2(b0.y, b1.y);
        xp[p][6] = pk2(b0.z, b1.z); xp[p][7] = pk2(b0.w, b1.w);
    }

    // Packed butterfly: reduce v[8] across the warp in 9 shfls, store partials.
    auto bstore = [&](const float v[LI], float dst[NW][LI]) {
        const bool h16 = (lane & 16);
        float a[4];
        #pragma unroll
        for (int j = 0; j < 4; j++) {
            float send = h16 ? v[j] : v[j + 4];
            float keep = h16 ? v[j + 4] : v[j];
            a[j] = keep + __shfl_xor_sync(FULL, send, 16);
        }
        const bool h8 = (lane & 8);
        float s0 = h8 ? a[0] : a[2], k0 = h8 ? a[2] : a[0];
        float b0 = k0 + __shfl_xor_sync(FULL, s0, 8);
        float s1 = h8 ? a[1] : a[3], k1 = h8 ? a[3] : a[1];
        float b1 = k1 + __shfl_xor_sync(FULL, s1, 8);
        const bool h4 = (lane & 4);
        float s2 = h4 ? b0 : b1, k2 = h4 ? b1 : b0;
        float c = k2 + __shfl_xor_sync(FULL, s2, 4);
        c += __shfl_xor_sync(FULL, c, 2);
        c += __shfl_xor_sync(FULL, c, 1);
        if ((lane & 3) == 0) dst[warp][lane >> 2] = c;
    };

    // ---- init: t = sum_n x[n] (scale-free) ----
    {
        float t[LI];
        #pragma unroll
        for (int i = 0; i < LI; i++) {
            unsigned long long s01 = fadd2(xp[0][i], xp[1][i]);
            unsigned long long s23 = fadd2(xp[2][i], xp[3][i]);
            unsigned long long s45 = fadd2(xp[4][i], xp[5][i]);
            unsigned long long s67 = fadd2(xp[6][i], xp[7][i]);
            unsigned long long s   = fadd2(fadd2(fadd2(s01, s23), fadd2(s45, s67)), xp[8][i]);
            float lo, hi; upk2(lo, hi, s);
            t[i] = lo + hi;
        }
        bstore(t, tred[0]);
    }
    __syncthreads();   // ws + tred[0] visible

    // ---- M = W^T W (one entry per thread, 64 entries) ----
    {
        const int i = tid >> 3, j = tid & 7;
        float m = 0.0f;
        #pragma unroll
        for (int l = 0; l < LO; l++) m = fmaf(ws[l * LI + i], ws[l * LI + j], m);
        Msh[tid] = m;
    }
    __syncthreads();   // Msh visible

    unsigned long long e2[NPAIR];   // last-iteration unnormalized probs

    #pragma unroll
    for (int it = 0; it < 3; it++) {
        const int rb = it & 1;

        // -- v_i = (M t)_i * rsqrt(t·Mt), i = lane&7 (replicated across lane groups) --
        const int i8 = lane & 7;
        float tl = tred[rb][0][i8] + tred[rb][1][i8];
        float g = 0.0f;
        #pragma unroll
        for (int j = 0; j < LI; j++) {
            float tj = __shfl_sync(FULL, tl, j);
            g = fmaf(Msh[i8 * LI + j], tj, g);
        }
        float sq = tl * g;
        sq += __shfl_xor_sync(FULL, sq, 4);
        sq += __shfl_xor_sync(FULL, sq, 2);
        sq += __shfl_xor_sync(FULL, sq, 1);
        float vi = g * rsqrtf(sq);

        // -- logits for 18 owned rows, packed: 9 FFMA2 per j --
        unsigned long long acc2[NPAIR];
        #pragma unroll
        for (int p = 0; p < NPAIR; p++) acc2[p] = 0ull;
        #pragma unroll
        for (int j = 0; j < LI; j++) {
            float vj = __shfl_sync(FULL, vi, j);
            unsigned long long vj2 = pk2(vj, vj);
            #pragma unroll
            for (int p = 0; p < NPAIR; p++) acc2[p] = ffma2(vj2, xp[p][j], acc2[p]);
        }

        // -- max-free exp (|logit| small: safe in fp32) --
        #pragma unroll
        for (int p = 0; p < NPAIR; p++) {
            float a0, a1; upk2(a0, a1, acc2[p]);
            e2[p] = pk2(__expf(a0), __expf(a1));
        }

        // last iteration: reduce softmax sum S
        if (it == 2) {
            unsigned long long s01 = fadd2(e2[0], e2[1]);
            unsigned long long s23 = fadd2(e2[2], e2[3]);
            unsigned long long s45 = fadd2(e2[4], e2[5]);
            unsigned long long s67 = fadd2(e2[6], e2[7]);
            unsigned long long sp  = fadd2(fadd2(fadd2(s01, s23), fadd2(s45, s67)), e2[8]);
            float lo, hi; upk2(lo, hi, sp);
            float S = lo + hi;
            S += __shfl_xor_sync(FULL, S, 16);
            S += __shfl_xor_sync(FULL, S, 8);
            S += __shfl_xor_sync(FULL, S, 4);
            S += __shfl_xor_sync(FULL, S, 2);
            S += __shfl_xor_sync(FULL, S, 1);
            if (lane == 0) sred[warp] = S;
        }

        // -- new t partial: t = Σ_k e_k x_k (packed), halves summed at the end --
        float t[LI];
        #pragma unroll
        for (int i = 0; i < LI; i++) {
            unsigned long long s = fmul2(e2[0], xp[0][i]);
            #pragma unroll
            for (int p = 1; p < NPAIR; p++) s = ffma2(e2[p], xp[p][i], s);
            float lo, hi; upk2(lo, hi, s);
            t[i] = lo + hi;
        }
        bstore(t, tred[rb ^ 1]);
        __syncthreads();
    }

    // ---- outputs ----
    const float S = sred[0] + sred[1];
    const float inv = __fdividef(1.0f, S);

    float* pp = out_p + (size_t)bo * N_IN;
    #pragma unroll
    for (int p = 0; p < NPAIR; p++) {
        float a0, a1; upk2(a0, a1, e2[p]);
        pp[tid + (2 * p) * THREADS]     = a0 * inv;
        pp[tid + (2 * p + 1) * THREADS] = a1 * inv;
    }

    if (tid < LO) {   // final centroid: out = W t_final / S  (iter2 wrote buf 1)
        float a = 0.0f;
        #pragma unroll
        for (int j = 0; j < LI; j++) {
            float tj = tred[1][0][j] + tred[1][1][j];
            a = fmaf(ws[tid * LI + j], tj, a);
        }
        out_c[(size_t)bo * LO + tid] = a * inv;
    }
}

extern "C" void kernel_launch(void* const* d_in, const int* in_sizes, int n_in,
                              void* d_out, int out_size)
{
    const float* x = (const float*)d_in[0];   // [64,1152,8]
    const float* w = (const float*)d_in[1];   // [64,16,8]
    float* out_c = (float*)d_out;                          // [64,64,16]
    float* out_p = out_c + (size_t)BATCH * O_CAPS * LO;    // [64,64,1152]

    caps_route_kernel<<<BATCH * O_CAPS, THREADS>>>(x, w, out_c, out_p);
}

// round 4
// speedup vs baseline: 1.5397x; 1.5397x over previous
#include <cuda_runtime.h>
#include <cuda_bf16.h>

// CapsuleLinear k-means routing (dot sim, no squash) — GB300 sm_103a, round 4.
//
// Reformulation (priors never materialized):
//   logits[n] = (W^T out_n)·x[n],  out ∝ W t,  t = Σ_n e_n x[n]
//   v = M t / sqrt(t^T M t),  M = W^T W  (8x8 per o, in smem)
// Softmax max-free; unnormalized except final iteration (scale invariance).
//
// Round-4: all-scalar FMA (r3 f32x2 packing regressed), TWO o-capsules per
// CTA sharing the same x-register tile. 128 threads x 9 rows. Lanes 0-7/8-15
// run the v-epilogue for o0/o1 via width-8 segment shuffles; one 16-component
// packed butterfly (16 shfls) reduces both t vectors. 1 barrier/iteration.

namespace {
constexpr int BATCH   = 64;
constexpr int N_IN    = 1152;
constexpr int LI      = 8;
constexpr int LO      = 16;
constexpr int O_CAPS  = 64;
constexpr int THREADS = 128;
constexpr int NPT     = 9;            // 1152 = 128 * 9
constexpr int NW      = THREADS / 32; // 4 warps
constexpr unsigned FULL = 0xffffffffu;
}

__global__ __launch_bounds__(THREADS, 4)
void caps_route_kernel(const float* __restrict__ x,
                       const float* __restrict__ wgt,
                       float* __restrict__ out_c,
                       float* __restrict__ out_p)
{
    const int bo2  = blockIdx.x;          // b*32 + opair (o fastest -> L2 reuse of x[b])
    const int b    = bo2 >> 5;
    const int o0   = (bo2 & 31) << 1;     // this CTA handles o0, o0+1
    const int tid  = threadIdx.x;
    const int lane = tid & 31;
    const int warp = tid >> 5;

    __shared__ float ws[2 * LO * LI];      // weights for o0, o1 (256 f32)
    __shared__ float Msh[2 * LI * LI];     // M = W^T W for o0, o1
    __shared__ float tred[2][NW][16];      // double-buffered t partials (o0:0-7, o1:8-15)
    __shared__ float sred[NW][2];          // final softmax sums

    const float* wb = wgt + (size_t)o0 * LO * LI;
    ws[tid]       = wb[tid];
    ws[tid + 128] = wb[tid + 128];

    // ---- x rows in registers: n = tid + k*128 (shared by both o's) ----
    float xr[NPT][LI];
    const float4* xb = reinterpret_cast<const float4*>(x + (size_t)b * N_IN * LI);
    #pragma unroll
    for (int k = 0; k < NPT; k++) {
        const int n = tid + k * THREADS;
        float4 a = xb[2 * n];
        float4 c = xb[2 * n + 1];
        xr[k][0] = a.x; xr[k][1] = a.y; xr[k][2] = a.z; xr[k][3] = a.w;
        xr[k][4] = c.x; xr[k][5] = c.y; xr[k][6] = c.z; xr[k][7] = c.w;
    }

    // Packed butterfly: reduce v[16] across warp in 16 shfls.
    // Final: lanes with (lane&1)==0 hold component (lane>>1)&15.
    auto bstore16 = [&](const float v[16], float dst[NW][16]) {
        const bool h16 = (lane & 16);
        float a[8];
        #pragma unroll
        for (int j = 0; j < 8; j++) {
            float send = h16 ? v[j] : v[j + 8];
            float keep = h16 ? v[j + 8] : v[j];
            a[j] = keep + __shfl_xor_sync(FULL, send, 16);
        }
        const bool h8 = (lane & 8);
        float bb[4];
        #pragma unroll
        for (int j = 0; j < 4; j++) {
            float send = h8 ? a[j] : a[j + 4];
            float keep = h8 ? a[j + 4] : a[j];
            bb[j] = keep + __shfl_xor_sync(FULL, send, 8);
        }
        const bool h4 = (lane & 4);
        float cc[2];
        #pragma unroll
        for (int j = 0; j < 2; j++) {
            float send = h4 ? bb[j] : bb[j + 2];
            float keep = h4 ? bb[j + 2] : bb[j];
            cc[j] = keep + __shfl_xor_sync(FULL, send, 4);
        }
        const bool h2 = (lane & 2);
        float send = h2 ? cc[0] : cc[1];
        float keep = h2 ? cc[1] : cc[0];
        float d = keep + __shfl_xor_sync(FULL, send, 2);
        d += __shfl_xor_sync(FULL, d, 1);
        if (!(lane & 1)) dst[warp][(lane >> 1) & 15] = d;
    };

    // ---- init: t = sum_n x[n] (scale-free), duplicated into both halves ----
    {
        float t16[16];
        #pragma unroll
        for (int i = 0; i < LI; i++) {
            float s01 = xr[0][i] + xr[1][i];
            float s23 = xr[2][i] + xr[3][i];
            float s45 = xr[4][i] + xr[5][i];
            float s67 = xr[6][i] + xr[7][i];
            float s = ((s01 + s23) + (s45 + s67)) + xr[8][i];
            t16[i] = s; t16[i + 8] = s;
        }
        bstore16(t16, tred[0]);
    }
    __syncthreads();   // ws + tred[0] visible

    // ---- M = W^T W for both o's (one entry per thread, 128 entries) ----
    {
        const int osel = tid >> 6;
        const int idx  = tid & 63;
        const int i = idx >> 3, j = idx & 7;
        const float* wsb = ws + osel * LO * LI;
        float m = 0.0f;
        #pragma unroll
        for (int l = 0; l < LO; l++) m = fmaf(wsb[l * LI + i], wsb[l * LI + j], m);
        Msh[tid] = m;
    }
    __syncthreads();   // Msh visible

    float e0[NPT], e1[NPT];   // last-iteration unnormalized probs

    #pragma unroll
    for (int it = 0; it < 3; it++) {
        const int rb = it & 1;

        // -- per-segment epilogue: lanes {0-7,16-23} -> o0, {8-15,24-31} -> o1 --
        const int i8   = lane & 7;
        const int osel = (lane >> 3) & 1;
        const int ti   = osel * 8 + i8;
        float tl = tred[rb][0][ti] + tred[rb][1][ti] + tred[rb][2][ti] + tred[rb][3][ti];
        float g = 0.0f;
        const float* Mrow = Msh + osel * 64 + i8 * LI;
        #pragma unroll
        for (int j = 0; j < LI; j++) {
            float tj = __shfl_sync(FULL, tl, j, 8);    // broadcast within 8-lane segment
            g = fmaf(Mrow[j], tj, g);
        }
        float sq = tl * g;
        sq += __shfl_xor_sync(FULL, sq, 4, 8);
        sq += __shfl_xor_sync(FULL, sq, 2, 8);
        sq += __shfl_xor_sync(FULL, sq, 1, 8);
        float vi = g * rsqrtf(sq);

        // -- logits for 9 rows x 2 o's (v broadcast via width-16 shfl) --
        float a0[NPT], a1[NPT];
        #pragma unroll
        for (int k = 0; k < NPT; k++) { a0[k] = 0.0f; a1[k] = 0.0f; }
        #pragma unroll
        for (int j = 0; j < LI; j++) {
            float vj0 = __shfl_sync(FULL, vi, j, 16);
            float vj1 = __shfl_sync(FULL, vi, 8 + j, 16);
            #pragma unroll
            for (int k = 0; k < NPT; k++) {
                a0[k] = fmaf(vj0, xr[k][j], a0[k]);
                a1[k] = fmaf(vj1, xr[k][j], a1[k]);
            }
        }

        // -- max-free exp --
        #pragma unroll
        for (int k = 0; k < NPT; k++) { e0[k] = __expf(a0[k]); e1[k] = __expf(a1[k]); }

        // last iteration: reduce both softmax sums (packed 2-value butterfly)
        if (it == 2) {
            float s0 = 0.0f, s1 = 0.0f;
            #pragma unroll
            for (int k = 0; k < NPT; k++) { s0 += e0[k]; s1 += e1[k]; }
            const bool h16 = (lane & 16);
            float send = h16 ? s0 : s1;
            float keep = h16 ? s1 : s0;
            float s = keep + __shfl_xor_sync(FULL, send, 16);
            s += __shfl_xor_sync(FULL, s, 8);
            s += __shfl_xor_sync(FULL, s, 4);
            s += __shfl_xor_sync(FULL, s, 2);
            s += __shfl_xor_sync(FULL, s, 1);
            if ((lane & 15) == 0) sred[warp][lane >> 4] = s;
        }

        // -- new t partials for both o's --
        float t16[16];
        #pragma unroll
        for (int i = 0; i < LI; i++) {
            float u0 = e0[0] * xr[0][i];
            float u1 = e1[0] * xr[0][i];
            #pragma unroll
            for (int k = 1; k < NPT; k++) {
                u0 = fmaf(e0[k], xr[k][i], u0);
                u1 = fmaf(e1[k], xr[k][i], u1);
            }
            t16[i] = u0; t16[i + 8] = u1;
        }
        bstore16(t16, tred[rb ^ 1]);
        __syncthreads();
    }

    // ---- outputs ----
    const float S0 = sred[0][0] + sred[1][0] + sred[2][0] + sred[3][0];
    const float S1 = sred[0][1] + sred[1][1] + sred[2][1] + sred[3][1];
    const float inv0 = __fdividef(1.0f, S0);
    const float inv1 = __fdividef(1.0f, S1);

    float* pp0 = out_p + (size_t)(b * O_CAPS + o0) * N_IN;
    float* pp1 = pp0 + N_IN;
    #pragma unroll
    for (int k = 0; k < NPT; k++) {
        pp0[tid + k * THREADS] = e0[k] * inv0;
        pp1[tid + k * THREADS] = e1[k] * inv1;
    }

    if (tid < 32) {   // final centroids (iter2 wrote tred buf 1)
        const int osel = tid >> 4;
        const int l    = tid & 15;
        const float* wsb = ws + osel * LO * LI + l * LI;
        float a = 0.0f;
        #pragma unroll
        for (int j = 0; j < LI; j++) {
            const int ti = osel * 8 + j;
            float tj = tred[1][0][ti] + tred[1][1][ti] + tred[1][2][ti] + tred[1][3][ti];
            a = fmaf(wsb[j], tj, a);
        }
        out_c[(size_t)(b * O_CAPS + o0 + osel) * LO + l] = a * (osel ? inv1 : inv0);
    }
}

extern "C" void kernel_launch(void* const* d_in, const int* in_sizes, int n_in,
                              void* d_out, int out_size)
{
    const float* x = (const float*)d_in[0];   // [64,1152,8]
    const float* w = (const float*)d_in[1];   // [64,16,8]
    float* out_c = (float*)d_out;                          // [64,64,16]
    float* out_p = out_c + (size_t)BATCH * O_CAPS * LO;    // [64,64,1152]

    caps_route_kernel<<<BATCH * O_CAPS / 2, THREADS>>>(x, w, out_c, out_p);
}